// round 10
// baseline (speedup 1.0000x reference)
#include <cuda_runtime.h>
#include <cuda_bf16.h>
#include <math.h>

// ---------------------------------------------------------------------------
// DetectorNetwork round 10: RECIPROCAL-MULTIPLY DUST EMULATION.
//   bh = m * fl(1/7)  (XLA fast-math lowering of /7), all bin edges computed
//   in f32 with __fmul_rn (no FMA), floor/ceil, +rs, clip [0,50].
//   fl(1/7) > 1/7 makes ceil((ph+1)*bh) land at m+1 for a per-m-selective
//   subset of boxes -> the extra end-rows the probe forensics demand.
//   Rest of pipeline identical to round 9 (biases bound from inputs).
// ---------------------------------------------------------------------------

#define Cc      512
#define Nn      512
#define FLATs   25088          // 512*7*7
#define FVS     4096

__device__ float g_A[1024 * FLATs];
__device__ float g_col[8192 * 8192];
__device__ float g_conv[8192 * 512];
__device__ float g_x1[8192 * 512];
__device__ float g_x2[8192 * 512];
__device__ float g_ns[512];
__device__ float g_y6[1024 * FVS];
__device__ float g_y7[1024 * FVS];
__device__ float g_cls[1024 * 21];
__device__ float g_reg[1024 * 80];
__device__ float g_zero_bias[4096];   // fallback zeros

// ---------------------------------------------------------------------------
// ROI max pool, f32 geometry with reciprocal-multiply bin width.
// ---------------------------------------------------------------------------
__global__ void roi_pool_kernel(const float* __restrict__ fm,
                                const float* __restrict__ prop) {
    int n = blockIdx.x;
    float x1 = prop[n*4+1], y1 = prop[n*4+0], x2 = prop[n*4+3], y2 = prop[n*4+2];
    float rsw = rintf(x1 * 0.0625f), rsh = rintf(y1 * 0.0625f);
    float rew = rintf(x2 * 0.0625f), reh = rintf(y2 * 0.0625f);
    const float C7 = 1.0f / 7.0f;              // fl(1/7), slightly ABOVE 1/7
    float mh = fmaxf(reh - rsh + 1.0f, 1.0f);
    float mw = fmaxf(rew - rsw + 1.0f, 1.0f);
    float bh = __fmul_rn(mh, C7);              // XLA fast-math: m * (1/7)
    float bw = __fmul_rn(mw, C7);

    for (int p = threadIdx.x; p < FLATs; p += blockDim.x) {
        int ch   = p / 49;
        int cell = p - ch * 49;
        int ph   = cell / 7;
        int pw   = cell - ph * 7;

        float hs = fminf(fmaxf(floorf(__fmul_rn((float)ph,     bh)) + rsh, 0.0f), 50.0f);
        float he = fminf(fmaxf(ceilf (__fmul_rn((float)(ph+1), bh)) + rsh, 0.0f), 50.0f);
        float ws = fminf(fmaxf(floorf(__fmul_rn((float)pw,     bw)) + rsw, 0.0f), 50.0f);
        float we = fminf(fmaxf(ceilf (__fmul_rn((float)(pw+1), bw)) + rsw, 0.0f), 50.0f);
        bool empty = (he <= hs) || (we <= ws);

        int hi = (int)hs, wi = (int)ws;
        int he_i = (int)he, we_i = (int)we;    // integral-valued floats
        // reference mask window is 10x10 from (hi,wi)
        if (he_i > hi + 10) he_i = hi + 10;
        if (we_i > wi + 10) we_i = wi + 10;

        float v = -INFINITY;
        const float* base = fm + (size_t)ch * 2500;
        for (int r = hi; r < he_i; ++r) {
            const float* row = base + r * 50;
            for (int c = wi; c < we_i; ++c) v = fmaxf(v, row[c]);
        }
        g_A[(size_t)n * FLATs + p] = (empty || v == -INFINITY) ? 0.0f : v;
    }
}

// ---------------------------------------------------------------------------
// im2col for the 4x4 VALID conv.
// ---------------------------------------------------------------------------
__global__ void im2col_kernel() {
    const long long total = 8192LL * 8192LL;
    for (long long idx = (long long)blockIdx.x * blockDim.x + threadIdx.x;
         idx < total; idx += (long long)gridDim.x * blockDim.x) {
        int m = (int)(idx >> 13);
        int k = (int)(idx & 8191);
        int n = m >> 4;
        int pcell = m & 15;
        int oy = pcell >> 2, ox = pcell & 3;
        int i = k >> 4;
        int q = k & 15;
        int ky = q >> 2, kx = q & 3;
        g_col[idx] = g_A[(size_t)n * FLATs + i * 49 + (oy + ky) * 7 + (ox + kx)];
    }
}

// ---------------------------------------------------------------------------
// SGEMM: C[M][N] = A[M][K]*B[N][K]^T + bias[N] (optional relu). K%8==0.
// ---------------------------------------------------------------------------
__global__ void __launch_bounds__(256, 2)
sgemm_kernel(const float* __restrict__ A, const float* __restrict__ B,
             const float* __restrict__ bias, float* __restrict__ C,
             int M, int N, int K, int doRelu) {
    __shared__ __align__(16) float As[8][128];
    __shared__ __align__(16) float Bs[8][128];

    int bm = blockIdx.y * 128;
    int bn = blockIdx.x * 128;
    int tid = threadIdx.x;
    int tx = tid & 15, ty = tid >> 4;
    int lr = tid >> 1;
    int lk = (tid & 1) * 4;

    const float* Aptr = A + (size_t)(bm + lr) * K + lk;
    const float* Bptr = B + (size_t)(bn + lr) * K + lk;
    bool aval = (bm + lr) < M;
    bool bval = (bn + lr) < N;

    float acc[8][8];
    #pragma unroll
    for (int i = 0; i < 8; ++i)
        #pragma unroll
        for (int j = 0; j < 8; ++j) acc[i][j] = 0.0f;

    for (int k0 = 0; k0 < K; k0 += 8) {
        float4 av = aval ? *(const float4*)Aptr : make_float4(0,0,0,0);
        float4 bv = bval ? *(const float4*)Bptr : make_float4(0,0,0,0);
        As[lk+0][lr] = av.x; As[lk+1][lr] = av.y; As[lk+2][lr] = av.z; As[lk+3][lr] = av.w;
        Bs[lk+0][lr] = bv.x; Bs[lk+1][lr] = bv.y; Bs[lk+2][lr] = bv.z; Bs[lk+3][lr] = bv.w;
        __syncthreads();

        #pragma unroll
        for (int kk = 0; kk < 8; ++kk) {
            float a[8], b[8];
            *(float4*)(&a[0]) = *(const float4*)(&As[kk][ty*8]);
            *(float4*)(&a[4]) = *(const float4*)(&As[kk][ty*8+4]);
            *(float4*)(&b[0]) = *(const float4*)(&Bs[kk][tx*8]);
            *(float4*)(&b[4]) = *(const float4*)(&Bs[kk][tx*8+4]);
            #pragma unroll
            for (int i = 0; i < 8; ++i)
                #pragma unroll
                for (int j = 0; j < 8; ++j)
                    acc[i][j] += a[i] * b[j];
        }
        __syncthreads();
        Aptr += 8; Bptr += 8;
    }

    #pragma unroll
    for (int i = 0; i < 8; ++i) {
        int row = bm + ty*8 + i;
        if (row >= M) continue;
        #pragma unroll
        for (int j = 0; j < 8; ++j) {
            int col = bn + tx*8 + j;
            if (col < N) {
                float v = acc[i][j] + bias[col];
                if (doRelu) v = fmaxf(v, 0.0f);
                C[(size_t)row * N + col] = v;
            }
        }
    }
}

__global__ void build_x1_kernel() {
    int idx = blockIdx.x * blockDim.x + threadIdx.x;
    if (idx >= 8192 * 512) return;
    int m = idx >> 9;
    int j = idx & 511;
    int n = m >> 4, g = m & 15;
    int o = g * 32 + (j >> 4);
    int pp = j & 15;
    g_x1[idx] = g_conv[(size_t)(n * 16 + pp) * 512 + o];
}

__global__ void fc2_ns_kernel(const float* __restrict__ w2,
                              const float* __restrict__ b2) {
    __shared__ float w2s[512];
    __shared__ float partial[16];
    int n = blockIdx.x;
    for (int j = threadIdx.x; j < 512; j += blockDim.x) w2s[j] = w2[j];
    __syncthreads();
    int warp = threadIdx.x >> 5, lane = threadIdx.x & 31;
    const float* row = g_x2 + (size_t)(n * 16 + warp) * 512;
    float s = 0.0f;
    for (int j = lane; j < 512; j += 32) s += row[j] * w2s[j];
    #pragma unroll
    for (int o = 16; o; o >>= 1) s += __shfl_xor_sync(0xffffffffu, s, o);
    if (lane == 0) {
        float b = b2 ? b2[0] : 0.0f;
        partial[warp] = 1.0f / (1.0f + expf(-(s + b)));
    }
    __syncthreads();
    if (threadIdx.x == 0) {
        float t = 0.0f;
        #pragma unroll
        for (int g = 0; g < 16; ++g) t += partial[g];
        g_ns[n] = t * (1.0f / 16.0f);
    }
}

__global__ void add_noise_kernel(const float* __restrict__ u) {
    const int total = Nn * FLATs;
    for (int idx = blockIdx.x * blockDim.x + threadIdx.x;
         idx < total; idx += gridDim.x * blockDim.x) {
        int n = idx / FLATs;
        int k = idx - n * FLATs;
        float noise = g_ns[n] * sqrtf(-2.0f * logf(u[idx]));
        g_A[(size_t)(512 + n) * FLATs + k] = g_A[(size_t)n * FLATs + k] + noise;
    }
}

__global__ void finalize_kernel(float* __restrict__ out) {
    int r = blockIdx.x;
    int t = threadIdx.x;
    bool nz = (r >= 512);
    int n = nz ? r - 512 : r;
    if (t < 32) {
        float v = (t < 21) ? g_cls[r * 21 + t] : -INFINITY;
        float m = v;
        #pragma unroll
        for (int o = 16; o; o >>= 1) m = fmaxf(m, __shfl_xor_sync(0xffffffffu, m, o));
        float e = (t < 21) ? expf(v - m) : 0.0f;
        float s = e;
        #pragma unroll
        for (int o = 16; o; o >>= 1) s += __shfl_xor_sync(0xffffffffu, s, o);
        if (t < 21) out[(nz ? 51712 : 0) + n * 21 + t] = e / s;
    } else if (t < 112) {
        int j = t - 32;
        out[(nz ? 62464 : 10752) + n * 80 + j] = g_reg[r * 80 + j];
    }
}

// ---------------------------------------------------------------------------
extern "C" void kernel_launch(void* const* d_in, const int* in_sizes, int n_in,
                              void* d_out, int out_size) {
    const float *feature_map = 0, *proposals = 0, *noise_u = 0;
    const float *np_conv_w = 0, *np_fc1_w = 0;
    const float *fc6_w = 0, *fc7_w = 0, *cls_w = 0, *reg_w = 0;
    const float *c512[3]  = {0, 0, 0};   // metadata order: conv_b, fc1_b, fc2_w
    const float *c4096[2] = {0, 0};      // metadata order: fc6_b, fc7_b
    const float *fc2_b = 0, *cls_b = 0, *reg_b = 0;
    int n512 = 0, n4096 = 0;
    for (int i = 0; i < n_in; ++i) {
        const float* p = (const float*)d_in[i];
        switch (in_sizes[i]) {
            case 1280000:   feature_map = p; break;
            case 2048:      proposals   = p; break;
            case 12845056:  noise_u     = p; break;
            case 4194304:   np_conv_w   = p; break;
            case 262144:    np_fc1_w    = p; break;
            case 102760448: fc6_w       = p; break;
            case 16777216:  fc7_w       = p; break;
            case 86016:     cls_w       = p; break;
            case 327680:    reg_w       = p; break;
            case 512:       if (n512  < 3) c512[n512++]   = p; break;
            case 4096:      if (n4096 < 2) c4096[n4096++] = p; break;
            case 1:         fc2_b = p; break;
            case 21:        cls_b = p; break;
            case 80:        reg_b = p; break;
            default: break;
        }
    }
    const float* np_conv_b = c512[0];
    const float* np_fc1_b  = c512[1];
    const float* np_fc2_w  = c512[2];
    const float* fc6_b     = c4096[0];
    const float* fc7_b     = c4096[1];
    float* out = (float*)d_out;

    float *pA, *pCol, *pConv, *pX1, *pX2, *pY6, *pY7, *pCls, *pReg, *pZb;
    cudaGetSymbolAddress((void**)&pA,   g_A);
    cudaGetSymbolAddress((void**)&pCol, g_col);
    cudaGetSymbolAddress((void**)&pConv,g_conv);
    cudaGetSymbolAddress((void**)&pX1,  g_x1);
    cudaGetSymbolAddress((void**)&pX2,  g_x2);
    cudaGetSymbolAddress((void**)&pY6,  g_y6);
    cudaGetSymbolAddress((void**)&pY7,  g_y7);
    cudaGetSymbolAddress((void**)&pCls, g_cls);
    cudaGetSymbolAddress((void**)&pReg, g_reg);
    cudaGetSymbolAddress((void**)&pZb,  g_zero_bias);
    if (!np_conv_b) np_conv_b = pZb;
    if (!np_fc1_b)  np_fc1_b  = pZb;
    if (!fc6_b)     fc6_b     = pZb;
    if (!fc7_b)     fc7_b     = pZb;
    if (!cls_b)     cls_b     = pZb;
    if (!reg_b)     reg_b     = pZb;

    roi_pool_kernel<<<512, 256>>>(feature_map, proposals);

    im2col_kernel<<<8192, 256>>>();
    {
        dim3 grid(512/128, 8192/128);
        sgemm_kernel<<<grid, 256>>>(pCol, np_conv_w, np_conv_b, pConv, 8192, 512, 8192, 1);
    }
    build_x1_kernel<<<(8192*512 + 255)/256, 256>>>();
    {
        dim3 grid(512/128, 8192/128);
        sgemm_kernel<<<grid, 256>>>(pX1, np_fc1_w, np_fc1_b, pX2, 8192, 512, 512, 1);
    }
    fc2_ns_kernel<<<512, 512>>>(np_fc2_w, fc2_b);

    add_noise_kernel<<<8192, 256>>>(noise_u);

    {
        dim3 grid(4096/128, 1024/128);
        sgemm_kernel<<<grid, 256>>>(pA, fc6_w, fc6_b, pY6, 1024, 4096, 25088, 1);
    }
    {
        dim3 grid(4096/128, 1024/128);
        sgemm_kernel<<<grid, 256>>>(pY6, fc7_w, fc7_b, pY7, 1024, 4096, 4096, 1);
    }
    {
        dim3 gridc(1, 1024/128);
        sgemm_kernel<<<gridc, 256>>>(pY7, cls_w, cls_b, pCls, 1024, 21, 4096, 0);
        dim3 gridr(1, 1024/128);
        sgemm_kernel<<<gridr, 256>>>(pY7, reg_w, reg_b, pReg, 1024, 80, 4096, 0);
    }

    finalize_kernel<<<1024, 128>>>(out);
}

// round 15
// speedup vs baseline: 1.5838x; 1.5838x over previous
#include <cuda_runtime.h>
#include <cuda_bf16.h>
#include <mma.h>
#include <math.h>

using namespace nvcuda;

// ---------------------------------------------------------------------------
// DetectorNetwork round 11: TF32 tensor-core GEMMs.
//   * roi_pool FROZEN from round 10 (reciprocal-multiply dust = passing)
//   * conv/fc1/fc6/fc7 -> wmma tf32 m16n16k8, 128x128 tile, double-buffered
//   * bias via 16-row replicated buffer loaded into accumulators
//   * heads remain fp32 sgemm (N=21/80), finalize unchanged
// ---------------------------------------------------------------------------

#define Cc      512
#define Nn      512
#define FLATs   25088          // 512*7*7
#define FVS     4096

__device__ float g_A[1024 * FLATs];
__device__ float g_col[8192 * 8192];
__device__ float g_conv[8192 * 512];
__device__ float g_x1[8192 * 512];
__device__ float g_x2[8192 * 512];
__device__ float g_ns[512];
__device__ float g_y6[1024 * FVS];
__device__ float g_y7[1024 * FVS];
__device__ float g_cls[1024 * 21];
__device__ float g_reg[1024 * 80];
__device__ float g_zero_bias[4096];
__device__ float g_brep[16 * 4096];     // replicated bias rows for wmma init

// ---------------------------------------------------------------------------
// ROI max pool — FROZEN (reciprocal-multiply dust; do not modify).
// ---------------------------------------------------------------------------
__global__ void roi_pool_kernel(const float* __restrict__ fm,
                                const float* __restrict__ prop) {
    int n = blockIdx.x;
    float x1 = prop[n*4+1], y1 = prop[n*4+0], x2 = prop[n*4+3], y2 = prop[n*4+2];
    float rsw = rintf(x1 * 0.0625f), rsh = rintf(y1 * 0.0625f);
    float rew = rintf(x2 * 0.0625f), reh = rintf(y2 * 0.0625f);
    const float C7 = 1.0f / 7.0f;
    float mh = fmaxf(reh - rsh + 1.0f, 1.0f);
    float mw = fmaxf(rew - rsw + 1.0f, 1.0f);
    float bh = __fmul_rn(mh, C7);
    float bw = __fmul_rn(mw, C7);

    for (int p = threadIdx.x; p < FLATs; p += blockDim.x) {
        int ch   = p / 49;
        int cell = p - ch * 49;
        int ph   = cell / 7;
        int pw   = cell - ph * 7;

        float hs = fminf(fmaxf(floorf(__fmul_rn((float)ph,     bh)) + rsh, 0.0f), 50.0f);
        float he = fminf(fmaxf(ceilf (__fmul_rn((float)(ph+1), bh)) + rsh, 0.0f), 50.0f);
        float ws = fminf(fmaxf(floorf(__fmul_rn((float)pw,     bw)) + rsw, 0.0f), 50.0f);
        float we = fminf(fmaxf(ceilf (__fmul_rn((float)(pw+1), bw)) + rsw, 0.0f), 50.0f);
        bool empty = (he <= hs) || (we <= ws);

        int hi = (int)hs, wi = (int)ws;
        int he_i = (int)he, we_i = (int)we;
        if (he_i > hi + 10) he_i = hi + 10;
        if (we_i > wi + 10) we_i = wi + 10;

        float v = -INFINITY;
        const float* base = fm + (size_t)ch * 2500;
        for (int r = hi; r < he_i; ++r) {
            const float* row = base + r * 50;
            for (int c = wi; c < we_i; ++c) v = fmaxf(v, row[c]);
        }
        g_A[(size_t)n * FLATs + p] = (empty || v == -INFINITY) ? 0.0f : v;
    }
}

// ---------------------------------------------------------------------------
// im2col for the 4x4 VALID conv.
// ---------------------------------------------------------------------------
__global__ void im2col_kernel() {
    const long long total = 8192LL * 8192LL;
    for (long long idx = (long long)blockIdx.x * blockDim.x + threadIdx.x;
         idx < total; idx += (long long)gridDim.x * blockDim.x) {
        int m = (int)(idx >> 13);
        int k = (int)(idx & 8191);
        int n = m >> 4;
        int pcell = m & 15;
        int oy = pcell >> 2, ox = pcell & 3;
        int i = k >> 4;
        int q = k & 15;
        int ky = q >> 2, kx = q & 3;
        g_col[idx] = g_A[(size_t)n * FLATs + i * 49 + (oy + ky) * 7 + (ox + kx)];
    }
}

// ---------------------------------------------------------------------------
// Replicate bias into 16 identical rows: g_brep[16][N]
// ---------------------------------------------------------------------------
__global__ void fill_biasrep(const float* __restrict__ bias, int N) {
    int i = blockIdx.x * blockDim.x + threadIdx.x;
    if (i < 16 * N) g_brep[i] = bias ? bias[i % N] : 0.0f;
}

// ---------------------------------------------------------------------------
// TF32 WMMA GEMM: C[M][N] = A[M][K]*B[N][K]^T + bias (replicated), opt relu.
// 128x128 tile, 8 warps (32x64 each), K-step 16, double-buffered smem.
// Requires: M%128==0, N%128==0, K%16==0, row pointers float4-aligned.
// ---------------------------------------------------------------------------
__global__ void __launch_bounds__(256, 2)
gemm_tf32(const float* __restrict__ A, const float* __restrict__ B,
          const float* __restrict__ brep, float* __restrict__ C,
          int M, int N, int K, int doRelu) {
    __shared__ float As[2][128][24];   // 24576 B
    __shared__ float Bs[2][128][24];   // 24576 B  (total = 48 KB exactly)

    int tid  = threadIdx.x;
    int warp = tid >> 5;
    int bm = blockIdx.y * 128;
    int bn = blockIdx.x * 128;

    // loader: each thread -> rows (lrow0, lrow0+64), k-cols [lc4, lc4+3]
    int lrow0 = tid >> 2;          // 0..63
    int lc4   = (tid & 3) * 4;     // 0,4,8,12

    const float* Aptr0 = A + (size_t)(bm + lrow0)      * K + lc4;
    const float* Aptr1 = A + (size_t)(bm + lrow0 + 64) * K + lc4;
    const float* Bptr0 = B + (size_t)(bn + lrow0)      * K + lc4;
    const float* Bptr1 = B + (size_t)(bn + lrow0 + 64) * K + lc4;

    // warp tile: rows r0..r0+31, cols c0..c0+63
    int wr = warp & 3, wc = warp >> 2;
    int r0 = wr * 32, c0 = wc * 64;

    wmma::fragment<wmma::accumulator, 16, 16, 8, float> acc[2][4];
    #pragma unroll
    for (int i = 0; i < 2; ++i)
        #pragma unroll
        for (int j = 0; j < 4; ++j)
            wmma::load_matrix_sync(acc[i][j], brep + (bn + c0 + j * 16), N,
                                   wmma::mem_row_major);

    int ntiles = K / 16;

    // prologue: tile 0 -> smem buf 0
    float4 a0 = *(const float4*)Aptr0;
    float4 a1 = *(const float4*)Aptr1;
    float4 b0 = *(const float4*)Bptr0;
    float4 b1 = *(const float4*)Bptr1;
    {
        float* d;
        d = &As[0][lrow0][lc4];
        d[0]=wmma::__float_to_tf32(a0.x); d[1]=wmma::__float_to_tf32(a0.y);
        d[2]=wmma::__float_to_tf32(a0.z); d[3]=wmma::__float_to_tf32(a0.w);
        d = &As[0][lrow0+64][lc4];
        d[0]=wmma::__float_to_tf32(a1.x); d[1]=wmma::__float_to_tf32(a1.y);
        d[2]=wmma::__float_to_tf32(a1.z); d[3]=wmma::__float_to_tf32(a1.w);
        d = &Bs[0][lrow0][lc4];
        d[0]=wmma::__float_to_tf32(b0.x); d[1]=wmma::__float_to_tf32(b0.y);
        d[2]=wmma::__float_to_tf32(b0.z); d[3]=wmma::__float_to_tf32(b0.w);
        d = &Bs[0][lrow0+64][lc4];
        d[0]=wmma::__float_to_tf32(b1.x); d[1]=wmma::__float_to_tf32(b1.y);
        d[2]=wmma::__float_to_tf32(b1.z); d[3]=wmma::__float_to_tf32(b1.w);
    }
    __syncthreads();

    for (int kt = 0; kt < ntiles; ++kt) {
        int buf = kt & 1;
        bool more = (kt + 1) < ntiles;
        if (more) {
            Aptr0 += 16; Aptr1 += 16; Bptr0 += 16; Bptr1 += 16;
            a0 = *(const float4*)Aptr0;
            a1 = *(const float4*)Aptr1;
            b0 = *(const float4*)Bptr0;
            b1 = *(const float4*)Bptr1;
        }

        #pragma unroll
        for (int kc = 0; kc < 16; kc += 8) {
            wmma::fragment<wmma::matrix_a, 16, 16, 8, wmma::precision::tf32,
                           wmma::row_major> af[2];
            wmma::fragment<wmma::matrix_b, 16, 16, 8, wmma::precision::tf32,
                           wmma::col_major> bf[4];
            #pragma unroll
            for (int i = 0; i < 2; ++i)
                wmma::load_matrix_sync(af[i], &As[buf][r0 + i * 16][kc], 24);
            #pragma unroll
            for (int j = 0; j < 4; ++j)
                wmma::load_matrix_sync(bf[j], &Bs[buf][c0 + j * 16][kc], 24);
            #pragma unroll
            for (int i = 0; i < 2; ++i)
                #pragma unroll
                for (int j = 0; j < 4; ++j)
                    wmma::mma_sync(acc[i][j], af[i], bf[j], acc[i][j]);
        }

        if (more) {
            int nb = buf ^ 1;
            float* d;
            d = &As[nb][lrow0][lc4];
            d[0]=wmma::__float_to_tf32(a0.x); d[1]=wmma::__float_to_tf32(a0.y);
            d[2]=wmma::__float_to_tf32(a0.z); d[3]=wmma::__float_to_tf32(a0.w);
            d = &As[nb][lrow0+64][lc4];
            d[0]=wmma::__float_to_tf32(a1.x); d[1]=wmma::__float_to_tf32(a1.y);
            d[2]=wmma::__float_to_tf32(a1.z); d[3]=wmma::__float_to_tf32(a1.w);
            d = &Bs[nb][lrow0][lc4];
            d[0]=wmma::__float_to_tf32(b0.x); d[1]=wmma::__float_to_tf32(b0.y);
            d[2]=wmma::__float_to_tf32(b0.z); d[3]=wmma::__float_to_tf32(b0.w);
            d = &Bs[nb][lrow0+64][lc4];
            d[0]=wmma::__float_to_tf32(b1.x); d[1]=wmma::__float_to_tf32(b1.y);
            d[2]=wmma::__float_to_tf32(b1.z); d[3]=wmma::__float_to_tf32(b1.w);
        }
        __syncthreads();
    }

    // epilogue: relu (elementwise, mapping-independent) + store
    #pragma unroll
    for (int i = 0; i < 2; ++i)
        #pragma unroll
        for (int j = 0; j < 4; ++j) {
            if (doRelu) {
                #pragma unroll
                for (int e = 0; e < acc[i][j].num_elements; ++e)
                    acc[i][j].x[e] = fmaxf(acc[i][j].x[e], 0.0f);
            }
            wmma::store_matrix_sync(
                C + (size_t)(bm + r0 + i * 16) * N + (bn + c0 + j * 16),
                acc[i][j], N, wmma::mem_row_major);
        }
}

// ---------------------------------------------------------------------------
// fp32 SGEMM (kept for the small heads; N=21/80 edge-predicated).
// ---------------------------------------------------------------------------
__global__ void __launch_bounds__(256, 2)
sgemm_kernel(const float* __restrict__ A, const float* __restrict__ B,
             const float* __restrict__ bias, float* __restrict__ C,
             int M, int N, int K, int doRelu) {
    __shared__ __align__(16) float As[8][128];
    __shared__ __align__(16) float Bs[8][128];

    int bm = blockIdx.y * 128;
    int bn = blockIdx.x * 128;
    int tid = threadIdx.x;
    int tx = tid & 15, ty = tid >> 4;
    int lr = tid >> 1;
    int lk = (tid & 1) * 4;

    const float* Aptr = A + (size_t)(bm + lr) * K + lk;
    const float* Bptr = B + (size_t)(bn + lr) * K + lk;
    bool aval = (bm + lr) < M;
    bool bval = (bn + lr) < N;

    float acc[8][8];
    #pragma unroll
    for (int i = 0; i < 8; ++i)
        #pragma unroll
        for (int j = 0; j < 8; ++j) acc[i][j] = 0.0f;

    for (int k0 = 0; k0 < K; k0 += 8) {
        float4 av = aval ? *(const float4*)Aptr : make_float4(0,0,0,0);
        float4 bv = bval ? *(const float4*)Bptr : make_float4(0,0,0,0);
        As[lk+0][lr] = av.x; As[lk+1][lr] = av.y; As[lk+2][lr] = av.z; As[lk+3][lr] = av.w;
        Bs[lk+0][lr] = bv.x; Bs[lk+1][lr] = bv.y; Bs[lk+2][lr] = bv.z; Bs[lk+3][lr] = bv.w;
        __syncthreads();

        #pragma unroll
        for (int kk = 0; kk < 8; ++kk) {
            float a[8], b[8];
            *(float4*)(&a[0]) = *(const float4*)(&As[kk][ty*8]);
            *(float4*)(&a[4]) = *(const float4*)(&As[kk][ty*8+4]);
            *(float4*)(&b[0]) = *(const float4*)(&Bs[kk][tx*8]);
            *(float4*)(&b[4]) = *(const float4*)(&Bs[kk][tx*8+4]);
            #pragma unroll
            for (int i = 0; i < 8; ++i)
                #pragma unroll
                for (int j = 0; j < 8; ++j)
                    acc[i][j] += a[i] * b[j];
        }
        __syncthreads();
        Aptr += 8; Bptr += 8;
    }

    #pragma unroll
    for (int i = 0; i < 8; ++i) {
        int row = bm + ty*8 + i;
        if (row >= M) continue;
        #pragma unroll
        for (int j = 0; j < 8; ++j) {
            int col = bn + tx*8 + j;
            if (col < N) {
                float v = acc[i][j] + bias[col];
                if (doRelu) v = fmaxf(v, 0.0f);
                C[(size_t)row * N + col] = v;
            }
        }
    }
}

__global__ void build_x1_kernel() {
    int idx = blockIdx.x * blockDim.x + threadIdx.x;
    if (idx >= 8192 * 512) return;
    int m = idx >> 9;
    int j = idx & 511;
    int n = m >> 4, g = m & 15;
    int o = g * 32 + (j >> 4);
    int pp = j & 15;
    g_x1[idx] = g_conv[(size_t)(n * 16 + pp) * 512 + o];
}

__global__ void fc2_ns_kernel(const float* __restrict__ w2,
                              const float* __restrict__ b2) {
    __shared__ float w2s[512];
    __shared__ float partial[16];
    int n = blockIdx.x;
    for (int j = threadIdx.x; j < 512; j += blockDim.x) w2s[j] = w2[j];
    __syncthreads();
    int warp = threadIdx.x >> 5, lane = threadIdx.x & 31;
    const float* row = g_x2 + (size_t)(n * 16 + warp) * 512;
    float s = 0.0f;
    for (int j = lane; j < 512; j += 32) s += row[j] * w2s[j];
    #pragma unroll
    for (int o = 16; o; o >>= 1) s += __shfl_xor_sync(0xffffffffu, s, o);
    if (lane == 0) {
        float b = b2 ? b2[0] : 0.0f;
        partial[warp] = 1.0f / (1.0f + expf(-(s + b)));
    }
    __syncthreads();
    if (threadIdx.x == 0) {
        float t = 0.0f;
        #pragma unroll
        for (int g = 0; g < 16; ++g) t += partial[g];
        g_ns[n] = t * (1.0f / 16.0f);
    }
}

__global__ void add_noise_kernel(const float* __restrict__ u) {
    const int total = Nn * FLATs;
    for (int idx = blockIdx.x * blockDim.x + threadIdx.x;
         idx < total; idx += gridDim.x * blockDim.x) {
        int n = idx / FLATs;
        int k = idx - n * FLATs;
        float noise = g_ns[n] * sqrtf(-2.0f * logf(u[idx]));
        g_A[(size_t)(512 + n) * FLATs + k] = g_A[(size_t)n * FLATs + k] + noise;
    }
}

__global__ void finalize_kernel(float* __restrict__ out) {
    int r = blockIdx.x;
    int t = threadIdx.x;
    bool nz = (r >= 512);
    int n = nz ? r - 512 : r;
    if (t < 32) {
        float v = (t < 21) ? g_cls[r * 21 + t] : -INFINITY;
        float m = v;
        #pragma unroll
        for (int o = 16; o; o >>= 1) m = fmaxf(m, __shfl_xor_sync(0xffffffffu, m, o));
        float e = (t < 21) ? expf(v - m) : 0.0f;
        float s = e;
        #pragma unroll
        for (int o = 16; o; o >>= 1) s += __shfl_xor_sync(0xffffffffu, s, o);
        if (t < 21) out[(nz ? 51712 : 0) + n * 21 + t] = e / s;
    } else if (t < 112) {
        int j = t - 32;
        out[(nz ? 62464 : 10752) + n * 80 + j] = g_reg[r * 80 + j];
    }
}

// ---------------------------------------------------------------------------
extern "C" void kernel_launch(void* const* d_in, const int* in_sizes, int n_in,
                              void* d_out, int out_size) {
    const float *feature_map = 0, *proposals = 0, *noise_u = 0;
    const float *np_conv_w = 0, *np_fc1_w = 0;
    const float *fc6_w = 0, *fc7_w = 0, *cls_w = 0, *reg_w = 0;
    const float *c512[3]  = {0, 0, 0};
    const float *c4096[2] = {0, 0};
    const float *fc2_b = 0, *cls_b = 0, *reg_b = 0;
    int n512 = 0, n4096 = 0;
    for (int i = 0; i < n_in; ++i) {
        const float* p = (const float*)d_in[i];
        switch (in_sizes[i]) {
            case 1280000:   feature_map = p; break;
            case 2048:      proposals   = p; break;
            case 12845056:  noise_u     = p; break;
            case 4194304:   np_conv_w   = p; break;
            case 262144:    np_fc1_w    = p; break;
            case 102760448: fc6_w       = p; break;
            case 16777216:  fc7_w       = p; break;
            case 86016:     cls_w       = p; break;
            case 327680:    reg_w       = p; break;
            case 512:       if (n512  < 3) c512[n512++]   = p; break;
            case 4096:      if (n4096 < 2) c4096[n4096++] = p; break;
            case 1:         fc2_b = p; break;
            case 21:        cls_b = p; break;
            case 80:        reg_b = p; break;
            default: break;
        }
    }
    const float* np_conv_b = c512[0];
    const float* np_fc1_b  = c512[1];
    const float* np_fc2_w  = c512[2];
    const float* fc6_b     = c4096[0];
    const float* fc7_b     = c4096[1];
    float* out = (float*)d_out;

    float *pA, *pCol, *pConv, *pX1, *pX2, *pY6, *pY7, *pCls, *pReg, *pZb, *pBr;
    cudaGetSymbolAddress((void**)&pA,   g_A);
    cudaGetSymbolAddress((void**)&pCol, g_col);
    cudaGetSymbolAddress((void**)&pConv,g_conv);
    cudaGetSymbolAddress((void**)&pX1,  g_x1);
    cudaGetSymbolAddress((void**)&pX2,  g_x2);
    cudaGetSymbolAddress((void**)&pY6,  g_y6);
    cudaGetSymbolAddress((void**)&pY7,  g_y7);
    cudaGetSymbolAddress((void**)&pCls, g_cls);
    cudaGetSymbolAddress((void**)&pReg, g_reg);
    cudaGetSymbolAddress((void**)&pZb,  g_zero_bias);
    cudaGetSymbolAddress((void**)&pBr,  g_brep);
    if (!np_conv_b) np_conv_b = pZb;
    if (!np_fc1_b)  np_fc1_b  = pZb;
    if (!fc6_b)     fc6_b     = pZb;
    if (!fc7_b)     fc7_b     = pZb;
    if (!cls_b)     cls_b     = pZb;
    if (!reg_b)     reg_b     = pZb;

    roi_pool_kernel<<<512, 256>>>(feature_map, proposals);

    im2col_kernel<<<8192, 256>>>();

    // conv: (8192 x 8192) * (512 x 8192)^T, relu
    fill_biasrep<<<(16*512 + 255)/256, 256>>>(np_conv_b, 512);
    {
        dim3 grid(512/128, 8192/128);
        gemm_tf32<<<grid, 256>>>(pCol, np_conv_w, pBr, pConv, 8192, 512, 8192, 1);
    }

    build_x1_kernel<<<(8192*512 + 255)/256, 256>>>();

    // fc1: (8192 x 512) * (512 x 512)^T, relu
    fill_biasrep<<<(16*512 + 255)/256, 256>>>(np_fc1_b, 512);
    {
        dim3 grid(512/128, 8192/128);
        gemm_tf32<<<grid, 256>>>(pX1, np_fc1_w, pBr, pX2, 8192, 512, 512, 1);
    }

    fc2_ns_kernel<<<512, 512>>>(np_fc2_w, fc2_b);

    add_noise_kernel<<<8192, 256>>>(noise_u);

    // fc6: (1024 x 25088) * (4096 x 25088)^T, relu
    fill_biasrep<<<(16*4096 + 255)/256, 256>>>(fc6_b, 4096);
    {
        dim3 grid(4096/128, 1024/128);
        gemm_tf32<<<grid, 256>>>(pA, fc6_w, pBr, pY6, 1024, 4096, 25088, 1);
    }

    // fc7: (1024 x 4096) * (4096 x 4096)^T, relu
    fill_biasrep<<<(16*4096 + 255)/256, 256>>>(fc7_b, 4096);
    {
        dim3 grid(4096/128, 1024/128);
        gemm_tf32<<<grid, 256>>>(pY6, fc7_w, pBr, pY7, 1024, 4096, 4096, 1);
    }

    // heads (fp32, edge-predicated)
    {
        dim3 gridc(1, 1024/128);
        sgemm_kernel<<<gridc, 256>>>(pY7, cls_w, cls_b, pCls, 1024, 21, 4096, 0);
        dim3 gridr(1, 1024/128);
        sgemm_kernel<<<gridr, 256>>>(pY7, reg_w, reg_b, pReg, 1024, 80, 4096, 0);
    }

    finalize_kernel<<<1024, 128>>>(out);
}